// round 4
// baseline (speedup 1.0000x reference)
#include <cuda_runtime.h>
#include <cstdint>

#define EPS 1e-5f
typedef unsigned long long ull;

// ---------------- scratch (device globals; zero-init at load; halos never written) ----------
__device__ __align__(16) float  g_h1[2*34*34*34*32];   // conv1 out, +1 halo all sides, channel-last
__device__ __align__(16) float  g_h2[2*32*32*32*32];   // conv2 out, channel-last [b][z][y][x][ci]
__device__ unsigned char        g_m1[2*32*32*32];      // conv1 output-site mask
__device__ __align__(16) float  g_w1t[27*32];          // W1  -> [tap][co]
__device__ __align__(16) float2 g_w2t[27*16*32];       // W2  -> [tap][ci/2][co] (ci-pair packed)
__device__ __align__(16) float2 g_wvt[27*16*100];      // Winv-> [tap][ci/2][co]

__device__ __forceinline__ ull ffma2(ull a, ull b, ull c){
    ull d; asm("fma.rn.f32x2 %0, %1, %2, %3;" : "=l"(d) : "l"(a), "l"(b), "l"(c)); return d;
}
__device__ __forceinline__ float pair_sum(ull v){
    float lo = __uint_as_float((unsigned)(v & 0xffffffffu));
    float hi = __uint_as_float((unsigned)(v >> 32));
    return lo + hi;
}

// ---------------- k0: weight transposes -----------------------------------------------------
__global__ void k0_transpose(const float* __restrict__ W1, const float* __restrict__ W2,
                             const float* __restrict__ Wv)
{
    const int N1 = 27*32;
    const int N2 = 27*16*32;
    const int N3 = 27*16*100;
    for (int i = blockIdx.x*blockDim.x + threadIdx.x; i < N1+N2+N3; i += gridDim.x*blockDim.x){
        if (i < N1){
            int tap = i >> 5, co = i & 31;
            g_w1t[i] = W1[co*27 + tap];
        } else if (i < N1+N2){
            int j = i - N1;
            int tap = j / 512, r = j % 512, cp = r >> 5, co = r & 31;
            g_w2t[j] = make_float2(W2[(co*32 + 2*cp    )*27 + tap],
                                   W2[(co*32 + 2*cp + 1)*27 + tap]);
        } else {
            int k = i - N1 - N2;
            int tap = k / 1600, r = k % 1600, cp = r / 100, co = r % 100;
            g_wvt[k] = make_float2(Wv[(co*32 + 2*cp    )*27 + tap],
                                   Wv[(co*32 + 2*cp + 1)*27 + tap]);
        }
    }
}

// ---------------- k1: conv1(s2) + BN + ReLU + mask  -> g_h1, g_m1 ----------------------------
__global__ __launch_bounds__(128)
void k1_conv1(const float* __restrict__ x, const int* __restrict__ mask0,
              const float* __restrict__ b1, const float* __restrict__ g1,
              const float* __restrict__ bt1, const float* __restrict__ rm1,
              const float* __restrict__ rv1)
{
    __shared__ float sin_[9][65];
    __shared__ int   smk[9][65];
    __shared__ float sw[27*32];
    __shared__ float m1f[32];

    const int yy = blockIdx.x, zz = blockIdx.y, b = blockIdx.z;
    const int t = threadIdx.x, co = t & 31, xg = t >> 5;

    for (int i = t; i < 9*65; i += 128){
        int r = i / 65, xx = i % 65;
        int kz = r / 3, ky = r % 3;
        int iz = 2*zz + kz, iy = 2*yy + ky;
        long off = ((long)(b*65 + iz)*65 + iy)*65 + xx;
        sin_[r][xx] = x[off];
        smk[r][xx]  = mask0[off];
    }
    for (int i = t; i < 27*32; i += 128) sw[i] = g_w1t[i];
    __syncthreads();

    if (t < 32){
        int xo = t, m = 0;
        #pragma unroll
        for (int r = 0; r < 9; r++)
            m |= smk[r][2*xo] | smk[r][2*xo+1] | smk[r][2*xo+2];
        m1f[xo] = m ? 1.0f : 0.0f;
        g_m1[((b*32 + zz)*32 + yy)*32 + xo] = m ? 1 : 0;
    }
    __syncthreads();

    const float s  = g1[co] * rsqrtf(rv1[co] + EPS);
    const float bb = bt1[co] - rm1[co]*s;
    const float bc = b1[co];

    for (int i = 0; i < 8; i++){
        int xo = xg + 4*i;
        float acc = 0.f;
        #pragma unroll
        for (int r = 0; r < 9; r++){
            #pragma unroll
            for (int kx = 0; kx < 3; kx++)
                acc = fmaf(sin_[r][2*xo + kx], sw[(r*3 + kx)*32 + co], acc);
        }
        float h = fmaxf((acc + bc)*s + bb, 0.f) * m1f[xo];
        g_h1[(((long)(b*34 + zz+1)*34 + (yy+1))*34 + (xo+1))*32 + co] = h;
    }
}

// ---------------- k2: SubMConv 32->32 + BN + ReLU + mask -> g_h2 (+ output zero-fill) --------
// grid (32 y, 32 z, 2 b), 128 threads: lane=co, 4 warps x 8 outputs each.
__global__ __launch_bounds__(128)
void k2_conv2(const float* __restrict__ b2, const float* __restrict__ g2,
              const float* __restrict__ bt2, const float* __restrict__ rm2,
              const float* __restrict__ rv2, float4* __restrict__ outz)
{
    __shared__ __align__(16) float sh[9*34*32];   // [row][px 0..33][ci] = 39168 B
    __shared__ float m1f[32];

    const int yy = blockIdx.x, zz = blockIdx.y, b = blockIdx.z;
    const int t = threadIdx.x, co = t & 31, w = t >> 5;
    const int x0 = w * 8;

    // stage 9 rows of padded h1 via float4
    {
        float4* dst = reinterpret_cast<float4*>(sh);
        for (int i = t; i < 2448; i += 128){
            int r = i / 272, rem = i % 272;
            int kz = r / 3, ky = r % 3;
            const float4* src = reinterpret_cast<const float4*>(
                g_h1 + (((long)(b*34 + zz+kz)*34 + (yy+ky))*34)*32);
            dst[r*272 + rem] = src[rem];
        }
        if (t < 32) m1f[t] = g_m1[((b*32 + zz)*32 + yy)*32 + t] ? 1.0f : 0.0f;
    }

    // embedded output zero-fill: 220MB rides the DRAM while we compute
    {
        const float4 z4 = make_float4(0.f,0.f,0.f,0.f);
        const int gid = (((b*32 + zz)*32 + yy)*128) + t;   // 0 .. 262143
        for (long i = gid; i < 13731250L; i += 262144L)
            outz[i] = z4;
    }
    __syncthreads();

    const ull* shu = reinterpret_cast<const ull*>(sh);
    const ull* w2u = reinterpret_cast<const ull*>(g_w2t);
    ull acc[8];
    #pragma unroll
    for (int j = 0; j < 8; j++) acc[j] = 0;

    for (int row = 0; row < 9; row++){
        const ull* base = shu + (row*34 + x0)*16;
        const ull* wb   = w2u + row*3*512 + co;
        #pragma unroll
        for (int cp = 0; cp < 16; cp++){
            ull h[10];
            #pragma unroll
            for (int i = 0; i < 10; i++) h[i] = base[i*16 + cp];
            ull w0 = __ldg(wb +           cp*32);
            ull w1 = __ldg(wb + 512     + cp*32);
            ull w2v= __ldg(wb + 1024    + cp*32);
            #pragma unroll
            for (int j = 0; j < 8; j++){
                acc[j] = ffma2(h[j  ], w0,  acc[j]);
                acc[j] = ffma2(h[j+1], w1,  acc[j]);
                acc[j] = ffma2(h[j+2], w2v, acc[j]);
            }
        }
    }

    const float s  = g2[co] * rsqrtf(rv2[co] + EPS);
    const float bb = bt2[co] - rm2[co]*s;
    const float bc = b2[co];
    float* out = g_h2 + (((long)(b*32 + zz)*32 + yy)*32)*32;
    #pragma unroll
    for (int j = 0; j < 8; j++){
        float v = fmaxf((pair_sum(acc[j]) + bc)*s + bb, 0.f) * m1f[x0+j];
        out[(x0+j)*32 + co] = v;
    }
}

// ---------------- k3: inverse conv 32->100 masked by mask0 -> d_out (sparse writes only) -----
// grid (65 y, 65 z, 2 b), 512 threads: slot = t/128 (4 x-slots), co = t%128 (<100 active)
__global__ __launch_bounds__(512)
void k3_inv(const int* __restrict__ mask0, const float* __restrict__ binv,
            float* __restrict__ out)
{
    __shared__ __align__(16) float sh[4*34*32];   // [zi*2+yi][px 0..33][ci] = 17408 B
    __shared__ int   alist[65];
    __shared__ int   s_na;
    __shared__ int   zq[2], zk[2], yq[2], yk[2], nZY[2];

    const int yy = blockIdx.x, zz = blockIdx.y, b = blockIdx.z;
    const int t = threadIdx.x;
    const long plane = (long)65*65*65;
    const long site  = ((long)zz*65 + yy)*65;

    if (t == 0){
        s_na = 0;
        if (zz & 1){ nZY[0]=1; zq[0]=(zz-1)>>1; zk[0]=1; zq[1]=-1; zk[1]=0; }
        else       { nZY[0]=2; zq[0]=(zz>>1)-1; zk[0]=0; zq[1]=zz>>1; zk[1]=2; }
        if (yy & 1){ nZY[1]=1; yq[0]=(yy-1)>>1; yk[0]=1; yq[1]=-1; yk[1]=0; }
        else       { nZY[1]=2; yq[0]=(yy>>1)-1; yk[0]=0; yq[1]=yy>>1; yk[1]=2; }
    }
    __syncthreads();
    if (t < 65){
        if (mask0[(long)b*plane + site + t]){
            int p = atomicAdd(&s_na, 1);
            alist[p] = t;
        }
    }
    __syncthreads();
    const int na = s_na;
    if (na == 0) return;

    const int nZ = nZY[0], nY = nZY[1];
    // stage candidate h2 rows into padded smem (zero halo at px=0/33; zero if q out of range)
    for (int f = t; f < 4*272; f += 512){
        int quad = f >> 8, rem = f & 255;            // 272 not pow2 -> handle via two passes
        // recompute properly: f in [0,1088): quad = f/272
        quad = f / 272; rem = f % 272;
        int zi = quad >> 1, yi = quad & 1;
        int px = rem >> 3, c4 = rem & 7;
        float4 v = make_float4(0.f,0.f,0.f,0.f);
        if (zi < nZ && yi < nY){
            int q0 = zq[zi], q1 = yq[yi];
            if (q0 >= 0 && q0 < 32 && q1 >= 0 && q1 < 32 && px >= 1 && px <= 32){
                const float4* src = reinterpret_cast<const float4*>(
                    g_h2 + (((long)(b*32 + q0)*32 + q1)*32)*32);
                v = src[(px-1)*8 + c4];
            }
        }
        reinterpret_cast<float4*>(sh + quad*34*32)[px*8 + c4] = v;
    }
    __syncthreads();

    const int slot = t >> 7, co = t & 127;
    if (co >= 100) return;
    const ull* shu = reinterpret_cast<const ull*>(sh);
    const ull* wvt = reinterpret_cast<const ull*>(g_wvt);
    const float bc = binv[co];
    float* orow = out + ((long)(b*100 + co))*plane + site;

    for (int ii = slot; ii < na; ii += 4){
        const int xx = alist[ii];
        ull acc0 = 0, acc1 = 0;
        const bool odd = xx & 1;
        const int pxA = odd ? ((xx+1) >> 1) : (xx >> 1);
        const int pxB = (xx >> 1) + 1;
        for (int zi = 0; zi < nZ; zi++){
            const int kz = zk[zi];
            for (int yi = 0; yi < nY; yi++){
                const int ky = yk[yi];
                const int tapb = (kz*3 + ky)*3;
                const ull* hrow = shu + (zi*2 + yi)*34*16;
                if (odd){
                    const ull* hp = hrow + pxA*16;
                    const ull* wp = wvt + (tapb + 1)*1600 + co;
                    #pragma unroll
                    for (int cp = 0; cp < 16; cp += 2){
                        acc0 = ffma2(hp[cp  ], __ldg(wp + cp*100      ), acc0);
                        acc1 = ffma2(hp[cp+1], __ldg(wp + cp*100 + 100), acc1);
                    }
                } else {
                    const ull* hpA = hrow + pxA*16;
                    const ull* hpB = hrow + pxB*16;
                    const ull* wpA = wvt + (tapb + 0)*1600 + co;
                    const ull* wpB = wvt + (tapb + 2)*1600 + co;
                    #pragma unroll
                    for (int cp = 0; cp < 16; cp++){
                        acc0 = ffma2(hpA[cp], __ldg(wpA + cp*100), acc0);
                        acc1 = ffma2(hpB[cp], __ldg(wpB + cp*100), acc1);
                    }
                }
            }
        }
        orow[xx] = pair_sum(acc0) + pair_sum(acc1) + bc;
    }
}

// ---------------- launch ---------------------------------------------------------------------
extern "C" void kernel_launch(void* const* d_in, const int* in_sizes, int n_in,
                              void* d_out, int out_size)
{
    const float* x     = (const float*)d_in[0];
    const int*   mask0 = (const int*)  d_in[1];
    const float* W1    = (const float*)d_in[2];
    const float* b1    = (const float*)d_in[3];
    const float* g1    = (const float*)d_in[4];
    const float* bt1   = (const float*)d_in[5];
    const float* rm1   = (const float*)d_in[6];
    const float* rv1   = (const float*)d_in[7];
    const float* W2    = (const float*)d_in[8];
    const float* b2    = (const float*)d_in[9];
    const float* g2    = (const float*)d_in[10];
    const float* bt2   = (const float*)d_in[11];
    const float* rm2   = (const float*)d_in[12];
    const float* rv2   = (const float*)d_in[13];
    const float* Winv  = (const float*)d_in[14];
    const float* binv  = (const float*)d_in[15];
    float* out = (float*)d_out;

    k0_transpose<<<64, 256>>>(W1, W2, Winv);
    k1_conv1<<<dim3(32,32,2), 128>>>(x, mask0, b1, g1, bt1, rm1, rv1);
    k2_conv2<<<dim3(32,32,2), 128>>>(b2, g2, bt2, rm2, rv2, (float4*)out);
    k3_inv  <<<dim3(65,65,2), 512>>>(mask0, binv, out);
}

// round 5
// speedup vs baseline: 1.2542x; 1.2542x over previous
#include <cuda_runtime.h>
#include <cstdint>

#define EPS 1e-5f
typedef unsigned long long ull;

// ---------------- scratch (device globals; zero-init at load; halos never written) ----------
__device__ __align__(16) float  g_h1[2*34*34*34*32];   // conv1 out, +1 halo all sides, channel-last
__device__ __align__(16) float  g_h2[2*32*32*32*32];   // conv2 out, channel-last [b][z][y][x][ci]
__device__ unsigned char        g_m1[2*32*32*32];      // conv1 output-site mask
__device__ __align__(16) float  g_w1t[27*32];          // W1  -> [tap][co]
__device__ __align__(16) float2 g_w2t[27*16*32];       // W2  -> [tap][ci/2][co] (ci-pair packed)
__device__ __align__(16) float2 g_wvt[27*16*100];      // Winv-> [tap][ci/2][co]

__device__ __forceinline__ ull ffma2(ull a, ull b, ull c){
    ull d; asm("fma.rn.f32x2 %0, %1, %2, %3;" : "=l"(d) : "l"(a), "l"(b), "l"(c)); return d;
}
__device__ __forceinline__ float pair_sum(ull v){
    float lo = __uint_as_float((unsigned)(v & 0xffffffffu));
    float hi = __uint_as_float((unsigned)(v >> 32));
    return lo + hi;
}

// ---------------- k0: weight transposes -----------------------------------------------------
__global__ void k0_transpose(const float* __restrict__ W1, const float* __restrict__ W2,
                             const float* __restrict__ Wv)
{
    const int N1 = 27*32;
    const int N2 = 27*16*32;
    const int N3 = 27*16*100;
    for (int i = blockIdx.x*blockDim.x + threadIdx.x; i < N1+N2+N3; i += gridDim.x*blockDim.x){
        if (i < N1){
            int tap = i >> 5, co = i & 31;
            g_w1t[i] = W1[co*27 + tap];
        } else if (i < N1+N2){
            int j = i - N1;
            int tap = j / 512, r = j % 512, cp = r >> 5, co = r & 31;
            g_w2t[j] = make_float2(W2[(co*32 + 2*cp    )*27 + tap],
                                   W2[(co*32 + 2*cp + 1)*27 + tap]);
        } else {
            int k = i - N1 - N2;
            int tap = k / 1600, r = k % 1600, cp = r / 100, co = r % 100;
            g_wvt[k] = make_float2(Wv[(co*32 + 2*cp    )*27 + tap],
                                   Wv[(co*32 + 2*cp + 1)*27 + tap]);
        }
    }
}

// ---------------- k1: conv1(s2) + BN + ReLU + mask  -> g_h1, g_m1 ----------------------------
__global__ __launch_bounds__(128)
void k1_conv1(const float* __restrict__ x, const int* __restrict__ mask0,
              const float* __restrict__ b1, const float* __restrict__ g1,
              const float* __restrict__ bt1, const float* __restrict__ rm1,
              const float* __restrict__ rv1)
{
    __shared__ float sin_[9][65];
    __shared__ int   smk[9][65];
    __shared__ float sw[27*32];
    __shared__ float m1f[32];

    const int yy = blockIdx.x, zz = blockIdx.y, b = blockIdx.z;
    const int t = threadIdx.x, co = t & 31, xg = t >> 5;

    for (int i = t; i < 9*65; i += 128){
        int r = i / 65, xx = i % 65;
        int kz = r / 3, ky = r % 3;
        int iz = 2*zz + kz, iy = 2*yy + ky;
        long off = ((long)(b*65 + iz)*65 + iy)*65 + xx;
        sin_[r][xx] = x[off];
        smk[r][xx]  = mask0[off];
    }
    for (int i = t; i < 27*32; i += 128) sw[i] = g_w1t[i];
    __syncthreads();

    if (t < 32){
        int xo = t, m = 0;
        #pragma unroll
        for (int r = 0; r < 9; r++)
            m |= smk[r][2*xo] | smk[r][2*xo+1] | smk[r][2*xo+2];
        m1f[xo] = m ? 1.0f : 0.0f;
        g_m1[((b*32 + zz)*32 + yy)*32 + xo] = m ? 1 : 0;
    }
    __syncthreads();

    const float s  = g1[co] * rsqrtf(rv1[co] + EPS);
    const float bb = bt1[co] - rm1[co]*s;
    const float bc = b1[co];

    for (int i = 0; i < 8; i++){
        int xo = xg + 4*i;
        float acc = 0.f;
        #pragma unroll
        for (int r = 0; r < 9; r++){
            #pragma unroll
            for (int kx = 0; kx < 3; kx++)
                acc = fmaf(sin_[r][2*xo + kx], sw[(r*3 + kx)*32 + co], acc);
        }
        float h = fmaxf((acc + bc)*s + bb, 0.f) * m1f[xo];
        g_h1[(((long)(b*34 + zz+1)*34 + (yy+1))*34 + (xo+1))*32 + co] = h;
    }
}

// ---------------- k2: SubMConv 32->32 + BN + ReLU + mask -> g_h2 (+ output zero-fill) --------
__global__ __launch_bounds__(128)
void k2_conv2(const float* __restrict__ b2, const float* __restrict__ g2,
              const float* __restrict__ bt2, const float* __restrict__ rm2,
              const float* __restrict__ rv2, float4* __restrict__ outz)
{
    __shared__ __align__(16) float sh[9*34*32];
    __shared__ float m1f[32];

    const int yy = blockIdx.x, zz = blockIdx.y, b = blockIdx.z;
    const int t = threadIdx.x, co = t & 31, w = t >> 5;
    const int x0 = w * 8;

    {
        float4* dst = reinterpret_cast<float4*>(sh);
        for (int i = t; i < 2448; i += 128){
            int r = i / 272, rem = i % 272;
            int kz = r / 3, ky = r % 3;
            const float4* src = reinterpret_cast<const float4*>(
                g_h1 + (((long)(b*34 + zz+kz)*34 + (yy+ky))*34)*32);
            dst[r*272 + rem] = src[rem];
        }
        if (t < 32) m1f[t] = g_m1[((b*32 + zz)*32 + yy)*32 + t] ? 1.0f : 0.0f;
    }

    // embedded 220MB output zero-fill: rides DRAM while we compute
    {
        const float4 z4 = make_float4(0.f,0.f,0.f,0.f);
        const int gid = (((b*32 + zz)*32 + yy)*128) + t;
        for (long i = gid; i < 13731250L; i += 262144L)
            outz[i] = z4;
    }
    __syncthreads();

    const ull* shu = reinterpret_cast<const ull*>(sh);
    const ull* w2u = reinterpret_cast<const ull*>(g_w2t);
    ull acc[8];
    #pragma unroll
    for (int j = 0; j < 8; j++) acc[j] = 0;

    for (int row = 0; row < 9; row++){
        const ull* base = shu + (row*34 + x0)*16;
        const ull* wb   = w2u + row*3*512 + co;
        #pragma unroll
        for (int cp = 0; cp < 16; cp++){
            ull h[10];
            #pragma unroll
            for (int i = 0; i < 10; i++) h[i] = base[i*16 + cp];
            ull w0 = __ldg(wb +        cp*32);
            ull w1 = __ldg(wb + 512  + cp*32);
            ull w2v= __ldg(wb + 1024 + cp*32);
            #pragma unroll
            for (int j = 0; j < 8; j++){
                acc[j] = ffma2(h[j  ], w0,  acc[j]);
                acc[j] = ffma2(h[j+1], w1,  acc[j]);
                acc[j] = ffma2(h[j+2], w2v, acc[j]);
            }
        }
    }

    const float s  = g2[co] * rsqrtf(rv2[co] + EPS);
    const float bb = bt2[co] - rm2[co]*s;
    const float bc = b2[co];
    float* out = g_h2 + (((long)(b*32 + zz)*32 + yy)*32)*32;
    #pragma unroll
    for (int j = 0; j < 8; j++){
        float v = fmaxf((pair_sum(acc[j]) + bc)*s + bb, 0.f) * m1f[x0+j];
        out[(x0+j)*32 + co] = v;
    }
}

// ---------------- k3 v3: parity-class blocks, weights cached in SMEM -------------------------
// grid (33 z-slices, 8 parity classes, 2 b), 512 threads: slot=t/128, co=t%128 (<100 active)
// dynamic smem: [0,102400) weights (<=8 taps * 1600 ull), [102400,..) site list (shorts)
#define K3_SMEM (102400 + 2304)
extern __shared__ __align__(16) unsigned char k3sm[];

__global__ __launch_bounds__(512)
void k3_inv(const int* __restrict__ mask0, const float* __restrict__ binv,
            float* __restrict__ out)
{
    ull* wsm = reinterpret_cast<ull*>(k3sm);
    unsigned short* alist = reinterpret_cast<unsigned short*>(k3sm + 102400);
    __shared__ int s_na;
    __shared__ int s_q0[2];
    __shared__ int s_q0v[2];

    const int cls = blockIdx.y;
    const int pz = cls >> 2, py = (cls >> 1) & 1, px = cls & 1;
    const int zz = pz + 2*(int)blockIdx.x;
    const int b  = blockIdx.z;
    if (zz > 64) return;

    const int nKZ = pz ? 1 : 2;
    const int nKY = py ? 1 : 2;
    const int nKX = px ? 1 : 2;
    const int nT  = nKZ*nKY*nKX;
    const int t = threadIdx.x;

    if (t == 0){
        s_na = 0;
        if (pz){ s_q0[0] = (zz-1)>>1; s_q0v[0] = 1; s_q0[1] = 0; s_q0v[1] = 0; }
        else {
            s_q0[0] = (zz>>1)-1; s_q0v[0] = (s_q0[0] >= 0);
            s_q0[1] = zz>>1;     s_q0v[1] = (s_q0[1] <= 31);
        }
    }

    // stage this class's weights: nT taps * 1600 ull, 16B chunks
    {
        const ulonglong2* src = reinterpret_cast<const ulonglong2*>(g_wvt);
        ulonglong2* dst = reinterpret_cast<ulonglong2*>(wsm);
        const int nyx = nKY*nKX;
        for (int i = t; i < nT*800; i += 512){
            int ti = i / 800, r = i - ti*800;
            int zi = ti / nyx, rr = ti - zi*nyx;
            int yi = rr / nKX, xi = rr - (rr/nKX)*nKX;
            int kz = pz ? 1 : zi*2;
            int ky = py ? 1 : yi*2;
            int kx = px ? 1 : xi*2;
            dst[ti*800 + r] = src[((kz*3 + ky)*3 + kx)*800 + r];
        }
    }
    __syncthreads();

    // build active-site list for this (class, zz, b)
    const int nYc = py ? 32 : 33;
    const int nXc = px ? 32 : 33;
    const long plane = 274625L;              // 65^3
    const long zbase = (long)b*plane + (long)zz*4225;
    for (int f = t; f < nYc*nXc; f += 512){
        int j = f / nXc, i = f - j*nXc;
        int yy = py + 2*j, xx = px + 2*i;
        if (mask0[zbase + yy*65 + xx]){
            int p = atomicAdd(&s_na, 1);
            alist[p] = (unsigned short)((yy << 8) | xx);
        }
    }
    __syncthreads();

    const int na = s_na;
    const int slot = t >> 7, co = t & 127;
    if (co >= 100) return;
    const float bc = binv[co];
    float* ob = out + ((long)(b*100 + co))*plane + (long)zz*4225;

    for (int ii = slot; ii < na; ii += 4){
        const int sv = alist[ii];
        const int yy = sv >> 8, xx = sv & 255;
        ull a0 = 0, a1 = 0, a2 = 0, a3 = 0;
        for (int zi = 0; zi < nKZ; zi++){
            if (!s_q0v[zi]) continue;
            const int q0 = s_q0[zi];
            for (int yi = 0; yi < nKY; yi++){
                const int q1 = py ? ((yy-1)>>1) : ((yy>>1) - 1 + yi);
                if ((unsigned)q1 > 31u) continue;
                for (int xi = 0; xi < nKX; xi++){
                    const int qx = px ? ((xx-1)>>1) : ((xx>>1) - 1 + xi);
                    if ((unsigned)qx > 31u) continue;
                    const int ti = (zi*nKY + yi)*nKX + xi;
                    const ulonglong2* hp = reinterpret_cast<const ulonglong2*>(
                        g_h2 + ((((long)(b*32 + q0)*32 + q1)*32 + qx) << 5));
                    const ull* wp = wsm + ti*1600 + co;
                    ull h[16];
                    #pragma unroll
                    for (int k = 0; k < 8; k++){
                        ulonglong2 v = __ldg(hp + k);
                        h[2*k] = v.x; h[2*k+1] = v.y;
                    }
                    #pragma unroll
                    for (int cp = 0; cp < 16; cp += 4){
                        a0 = ffma2(h[cp  ], wp[(cp  )*100], a0);
                        a1 = ffma2(h[cp+1], wp[(cp+1)*100], a1);
                        a2 = ffma2(h[cp+2], wp[(cp+2)*100], a2);
                        a3 = ffma2(h[cp+3], wp[(cp+3)*100], a3);
                    }
                }
            }
        }
        ob[yy*65 + xx] = pair_sum(a0) + pair_sum(a1) + pair_sum(a2) + pair_sum(a3) + bc;
    }
}

// ---------------- launch ---------------------------------------------------------------------
extern "C" void kernel_launch(void* const* d_in, const int* in_sizes, int n_in,
                              void* d_out, int out_size)
{
    const float* x     = (const float*)d_in[0];
    const int*   mask0 = (const int*)  d_in[1];
    const float* W1    = (const float*)d_in[2];
    const float* b1    = (const float*)d_in[3];
    const float* g1    = (const float*)d_in[4];
    const float* bt1   = (const float*)d_in[5];
    const float* rm1   = (const float*)d_in[6];
    const float* rv1   = (const float*)d_in[7];
    const float* W2    = (const float*)d_in[8];
    const float* b2    = (const float*)d_in[9];
    const float* g2    = (const float*)d_in[10];
    const float* bt2   = (const float*)d_in[11];
    const float* rm2   = (const float*)d_in[12];
    const float* rv2   = (const float*)d_in[13];
    const float* Winv  = (const float*)d_in[14];
    const float* binv  = (const float*)d_in[15];
    float* out = (float*)d_out;

    static int smem_set = 0;
    if (!smem_set){
        cudaFuncSetAttribute(k3_inv, cudaFuncAttributeMaxDynamicSharedMemorySize, K3_SMEM);
        smem_set = 1;
    }

    k0_transpose<<<64, 256>>>(W1, W2, Winv);
    k1_conv1<<<dim3(32,32,2), 128>>>(x, mask0, b1, g1, bt1, rm1, rv1);
    k2_conv2<<<dim3(32,32,2), 128>>>(b2, g2, bt2, rm2, rv2, (float4*)out);
    k3_inv  <<<dim3(33,8,2), 512, K3_SMEM>>>(mask0, binv, out);
}

// round 6
// speedup vs baseline: 1.5693x; 1.2513x over previous
#include <cuda_runtime.h>
#include <cstdint>

#define EPS 1e-5f
typedef unsigned long long ull;

// ---------------- scratch (device globals; zero-init at load; halos never written) ----------
__device__ __align__(16) float  g_h1[2*34*34*34*32];   // conv1 out, +1 halo all sides, channel-last
__device__ __align__(16) float  g_h2[2*32*32*32*32];   // conv2 out, channel-last [b][z][y][x][ci]
__device__ unsigned char        g_m1[2*32*32*32];      // conv1 output-site mask
__device__ __align__(16) float  g_w1t[27*32];          // W1  -> [tap][co]
__device__ __align__(16) float2 g_w2t[27*16*32];       // W2  -> [tap][ci/2][co] (ci-pair packed)
__device__ __align__(16) float2 g_wvt[27*16*100];      // Winv-> [tap][ci/2][co]

__device__ __forceinline__ ull ffma2(ull a, ull b, ull c){
    ull d; asm("fma.rn.f32x2 %0, %1, %2, %3;" : "=l"(d) : "l"(a), "l"(b), "l"(c)); return d;
}
__device__ __forceinline__ ull addf2(ull a, ull b){
    ull d; asm("add.rn.f32x2 %0, %1, %2;" : "=l"(d) : "l"(a), "l"(b)); return d;
}
__device__ __forceinline__ float pair_sum(ull v){
    float lo = __uint_as_float((unsigned)(v & 0xffffffffu));
    float hi = __uint_as_float((unsigned)(v >> 32));
    return lo + hi;
}

// ---------------- k0: weight transposes -----------------------------------------------------
__global__ void k0_transpose(const float* __restrict__ W1, const float* __restrict__ W2,
                             const float* __restrict__ Wv)
{
    const int N1 = 27*32;
    const int N2 = 27*16*32;
    const int N3 = 27*16*100;
    for (int i = blockIdx.x*blockDim.x + threadIdx.x; i < N1+N2+N3; i += gridDim.x*blockDim.x){
        if (i < N1){
            int tap = i >> 5, co = i & 31;
            g_w1t[i] = W1[co*27 + tap];
        } else if (i < N1+N2){
            int j = i - N1;
            int tap = j / 512, r = j % 512, cp = r >> 5, co = r & 31;
            g_w2t[j] = make_float2(W2[(co*32 + 2*cp    )*27 + tap],
                                   W2[(co*32 + 2*cp + 1)*27 + tap]);
        } else {
            int k = i - N1 - N2;
            int tap = k / 1600, r = k % 1600, cp = r / 100, co = r % 100;
            g_wvt[k] = make_float2(Wv[(co*32 + 2*cp    )*27 + tap],
                                   Wv[(co*32 + 2*cp + 1)*27 + tap]);
        }
    }
}

// ---------------- k1: conv1(s2) + BN + ReLU + mask  -> g_h1, g_m1 ----------------------------
__global__ __launch_bounds__(128)
void k1_conv1(const float* __restrict__ x, const int* __restrict__ mask0,
              const float* __restrict__ b1, const float* __restrict__ g1,
              const float* __restrict__ bt1, const float* __restrict__ rm1,
              const float* __restrict__ rv1)
{
    __shared__ float sin_[9][65];
    __shared__ int   smk[9][65];
    __shared__ float sw[27*32];
    __shared__ float m1f[32];

    const int yy = blockIdx.x, zz = blockIdx.y, b = blockIdx.z;
    const int t = threadIdx.x, co = t & 31, xg = t >> 5;

    for (int i = t; i < 9*65; i += 128){
        int r = i / 65, xx = i % 65;
        int kz = r / 3, ky = r % 3;
        int iz = 2*zz + kz, iy = 2*yy + ky;
        long off = ((long)(b*65 + iz)*65 + iy)*65 + xx;
        sin_[r][xx] = x[off];
        smk[r][xx]  = mask0[off];
    }
    for (int i = t; i < 27*32; i += 128) sw[i] = g_w1t[i];
    __syncthreads();

    if (t < 32){
        int xo = t, m = 0;
        #pragma unroll
        for (int r = 0; r < 9; r++)
            m |= smk[r][2*xo] | smk[r][2*xo+1] | smk[r][2*xo+2];
        m1f[xo] = m ? 1.0f : 0.0f;
        g_m1[((b*32 + zz)*32 + yy)*32 + xo] = m ? 1 : 0;
    }
    __syncthreads();

    const float s  = g1[co] * rsqrtf(rv1[co] + EPS);
    const float bb = bt1[co] - rm1[co]*s;
    const float bc = b1[co];

    for (int i = 0; i < 8; i++){
        int xo = xg + 4*i;
        float acc = 0.f;
        #pragma unroll
        for (int r = 0; r < 9; r++){
            #pragma unroll
            for (int kx = 0; kx < 3; kx++)
                acc = fmaf(sin_[r][2*xo + kx], sw[(r*3 + kx)*32 + co], acc);
        }
        float h = fmaxf((acc + bc)*s + bb, 0.f) * m1f[xo];
        g_h1[(((long)(b*34 + zz+1)*34 + (yy+1))*34 + (xo+1))*32 + co] = h;
    }
}

// ---------------- k2: SubMConv 32->32 + BN + ReLU + mask -> g_h2 (+ output zero-fill) --------
__global__ __launch_bounds__(128)
void k2_conv2(const float* __restrict__ b2, const float* __restrict__ g2,
              const float* __restrict__ bt2, const float* __restrict__ rm2,
              const float* __restrict__ rv2, float4* __restrict__ outz)
{
    __shared__ __align__(16) float sh[9*34*32];
    __shared__ float m1f[32];

    const int yy = blockIdx.x, zz = blockIdx.y, b = blockIdx.z;
    const int t = threadIdx.x, co = t & 31, w = t >> 5;
    const int x0 = w * 8;

    {
        float4* dst = reinterpret_cast<float4*>(sh);
        for (int i = t; i < 2448; i += 128){
            int r = i / 272, rem = i % 272;
            int kz = r / 3, ky = r % 3;
            const float4* src = reinterpret_cast<const float4*>(
                g_h1 + (((long)(b*34 + zz+kz)*34 + (yy+ky))*34)*32);
            dst[r*272 + rem] = src[rem];
        }
        if (t < 32) m1f[t] = g_m1[((b*32 + zz)*32 + yy)*32 + t] ? 1.0f : 0.0f;
    }

    // embedded 220MB output zero-fill: rides DRAM while we compute
    {
        const float4 z4 = make_float4(0.f,0.f,0.f,0.f);
        const int gid = (((b*32 + zz)*32 + yy)*128) + t;
        for (long i = gid; i < 13731250L; i += 262144L)
            outz[i] = z4;
    }
    __syncthreads();

    const ull* shu = reinterpret_cast<const ull*>(sh);
    const ull* w2u = reinterpret_cast<const ull*>(g_w2t);
    ull acc[8];
    #pragma unroll
    for (int j = 0; j < 8; j++) acc[j] = 0;

    for (int row = 0; row < 9; row++){
        const ull* base = shu + (row*34 + x0)*16;
        const ull* wb   = w2u + row*3*512 + co;
        #pragma unroll
        for (int cp = 0; cp < 16; cp++){
            ull h[10];
            #pragma unroll
            for (int i = 0; i < 10; i++) h[i] = base[i*16 + cp];
            ull w0 = __ldg(wb +        cp*32);
            ull w1 = __ldg(wb + 512  + cp*32);
            ull w2v= __ldg(wb + 1024 + cp*32);
            #pragma unroll
            for (int j = 0; j < 8; j++){
                acc[j] = ffma2(h[j  ], w0,  acc[j]);
                acc[j] = ffma2(h[j+1], w1,  acc[j]);
                acc[j] = ffma2(h[j+2], w2v, acc[j]);
            }
        }
    }

    const float s  = g2[co] * rsqrtf(rv2[co] + EPS);
    const float bb = bt2[co] - rm2[co]*s;
    const float bc = b2[co];
    float* out = g_h2 + (((long)(b*32 + zz)*32 + yy)*32)*32;
    #pragma unroll
    for (int j = 0; j < 8; j++){
        float v = fmaxf((pair_sum(acc[j]) + bc)*s + bb, 0.f) * m1f[x0+j];
        out[(x0+j)*32 + co] = v;
    }
}

// ---------------- k3 v4: tap-outer, weights in REGISTERS, smem site accumulator --------------
// grid (33 z-slices, 8 parity classes, 2 b), 512 threads: slot = t/128, co = t%128 (<100)
// dyn smem: acc[128*100]f (51200) | wS[1600]ull (12800) | alist[1089]u16
#define K3_NCH  128
#define K3_ACC_B 51200
#define K3_W_B   12800
#define K3_SMEM (K3_ACC_B + K3_W_B + 2192)
extern __shared__ __align__(16) unsigned char k3sm[];

__global__ __launch_bounds__(512)
void k3_inv(const int* __restrict__ mask0, const float* __restrict__ binv,
            float* __restrict__ out)
{
    float*          accS  = reinterpret_cast<float*>(k3sm);
    ull*            wS    = reinterpret_cast<ull*>(k3sm + K3_ACC_B);
    unsigned short* alist = reinterpret_cast<unsigned short*>(k3sm + K3_ACC_B + K3_W_B);
    __shared__ int s_na;

    const int cls = blockIdx.y;
    const int pz = cls >> 2, py = (cls >> 1) & 1, px = cls & 1;
    const int zz = pz + 2*(int)blockIdx.x;
    const int b  = blockIdx.z;
    if (zz > 64) return;

    const int nKZ = pz ? 1 : 2;
    const int nKY = py ? 1 : 2;
    const int nKX = px ? 1 : 2;
    const int nT  = nKZ*nKY*nKX;
    const int t = threadIdx.x;
    const int slot = t >> 7, co = t & 127;

    if (t == 0) s_na = 0;
    __syncthreads();

    // build active-site list for this (class, zz, b)
    const int nYc = py ? 32 : 33;
    const int nXc = px ? 32 : 33;
    const long plane = 274625L;              // 65^3
    const long zbase = (long)b*plane + (long)zz*4225;
    for (int f = t; f < nYc*nXc; f += 512){
        int j = f / nXc, i = f - j*nXc;
        int yy = py + 2*j, xx = px + 2*i;
        if (mask0[zbase + yy*65 + xx]){
            int p = atomicAdd(&s_na, 1);
            alist[p] = (unsigned short)((yy << 8) | xx);
        }
    }
    __syncthreads();
    const int na = s_na;
    if (na == 0) return;

    const float bc = (co < 100) ? binv[co] : 0.f;
    float* ob = out + ((long)(b*100 + co))*plane + (long)zz*4225;
    const ulonglong2* wsrc = reinterpret_cast<const ulonglong2*>(g_wvt);

    for (int c0 = 0; c0 < na; c0 += K3_NCH){
        const int nc = min(K3_NCH, na - c0);
        __syncthreads();                        // protect prev chunk writeout reads
        // zero accumulator
        {
            float4* a4 = reinterpret_cast<float4*>(accS);
            for (int i = t; i < K3_NCH*100/4; i += 512) a4[i] = make_float4(0,0,0,0);
        }
        __syncthreads();

        for (int ti = 0; ti < nT; ti++){
            const int nyx = nKY*nKX;
            const int zi = ti / nyx, rr = ti - zi*nyx;
            const int yi = rr / nKX, xi = rr - (rr/nKX)*nKX;
            const int q0 = pz ? ((zz-1) >> 1) : ((zz >> 1) - 1 + zi);
            if ((unsigned)q0 > 31u) continue;   // uniform over block: safe vs syncs
            const int kz = pz ? 1 : 2*zi;
            const int ky = py ? 1 : 2*yi;
            const int kx = px ? 1 : 2*xi;
            const int tap = (kz*3 + ky)*3 + kx;

            __syncthreads();                    // wS readers of prev tap done
            {
                ulonglong2* d2 = reinterpret_cast<ulonglong2*>(wS);
                const ulonglong2* s2 = wsrc + tap*800;
                for (int i = t; i < 800; i += 512) d2[i] = s2[i];
            }
            __syncthreads();

            if (co < 100){
                ull w[16];
                #pragma unroll
                for (int cp = 0; cp < 16; cp++) w[cp] = wS[cp*100 + co];

                const float* hbase = g_h2 + (((long)(b*32 + q0)) << 10)*32;
                for (int ii = slot; ii < nc; ii += 4){
                    const int sv = alist[c0 + ii];
                    const int yy = sv >> 8, xx = sv & 255;
                    const int q1 = py ? ((yy-1) >> 1) : ((yy >> 1) - 1 + yi);
                    const int qx = px ? ((xx-1) >> 1) : ((xx >> 1) - 1 + xi);
                    if (((unsigned)q1 > 31u) | ((unsigned)qx > 31u)) continue;
                    const ulonglong2* hp = reinterpret_cast<const ulonglong2*>(
                        hbase + ((q1*32 + qx) << 5));
                    ull a0 = 0, a1 = 0, a2 = 0, a3 = 0;
                    #pragma unroll
                    for (int k = 0; k < 4; k++){
                        ulonglong2 u = __ldg(hp + 2*k);
                        ulonglong2 v = __ldg(hp + 2*k + 1);
                        a0 = ffma2(u.x, w[4*k+0], a0);
                        a1 = ffma2(u.y, w[4*k+1], a1);
                        a2 = ffma2(v.x, w[4*k+2], a2);
                        a3 = ffma2(v.y, w[4*k+3], a3);
                    }
                    ull s = addf2(addf2(a0, a1), addf2(a2, a3));
                    accS[ii*100 + co] += pair_sum(s);
                }
            }
        }
        __syncthreads();                        // acc complete (zero-path threads too)

        if (co < 100){
            for (int ii = slot; ii < nc; ii += 4){
                const int sv = alist[c0 + ii];
                const int yy = sv >> 8, xx = sv & 255;
                ob[yy*65 + xx] = accS[ii*100 + co] + bc;
            }
        }
    }
}

// ---------------- launch ---------------------------------------------------------------------
extern "C" void kernel_launch(void* const* d_in, const int* in_sizes, int n_in,
                              void* d_out, int out_size)
{
    const float* x     = (const float*)d_in[0];
    const int*   mask0 = (const int*)  d_in[1];
    const float* W1    = (const float*)d_in[2];
    const float* b1    = (const float*)d_in[3];
    const float* g1    = (const float*)d_in[4];
    const float* bt1   = (const float*)d_in[5];
    const float* rm1   = (const float*)d_in[6];
    const float* rv1   = (const float*)d_in[7];
    const float* W2    = (const float*)d_in[8];
    const float* b2    = (const float*)d_in[9];
    const float* g2    = (const float*)d_in[10];
    const float* bt2   = (const float*)d_in[11];
    const float* rm2   = (const float*)d_in[12];
    const float* rv2   = (const float*)d_in[13];
    const float* Winv  = (const float*)d_in[14];
    const float* binv  = (const float*)d_in[15];
    float* out = (float*)d_out;

    static int smem_set = 0;
    if (!smem_set){
        cudaFuncSetAttribute(k3_inv, cudaFuncAttributeMaxDynamicSharedMemorySize, K3_SMEM);
        smem_set = 1;
    }

    k0_transpose<<<64, 256>>>(W1, W2, Winv);
    k1_conv1<<<dim3(32,32,2), 128>>>(x, mask0, b1, g1, bt1, rm1, rv1);
    k2_conv2<<<dim3(32,32,2), 128>>>(b2, g2, bt2, rm2, rv2, (float4*)out);
    k3_inv  <<<dim3(33,8,2), 512, K3_SMEM>>>(mask0, binv, out);
}

// round 7
// speedup vs baseline: 1.5989x; 1.0188x over previous
#include <cuda_runtime.h>
#include <cstdint>

#define EPS 1e-5f
typedef unsigned long long ull;

// ---------------- scratch (device globals; zero-init at load; halos never written) ----------
__device__ __align__(16) float  g_h1[2*34*34*34*32];   // conv1 out, +1 halo all sides, channel-last
__device__ __align__(16) float  g_h2[2*32*32*32*32];   // conv2 out, channel-last [b][z][y][x][ci]
__device__ unsigned char        g_m1[2*32*32*32];      // conv1 output-site mask
__device__ __align__(16) float  g_w1t[27*32];          // W1  -> [tap][co]
__device__ __align__(16) float2 g_w2t[27*16*32];       // W2  -> [tap][ci/2][co] (ci-pair packed)
__device__ __align__(16) float2 g_wvt[27*16*100];      // Winv-> [tap][ci/2][co]

__device__ __forceinline__ ull ffma2(ull a, ull b, ull c){
    ull d; asm("fma.rn.f32x2 %0, %1, %2, %3;" : "=l"(d) : "l"(a), "l"(b), "l"(c)); return d;
}
__device__ __forceinline__ ull addf2(ull a, ull b){
    ull d; asm("add.rn.f32x2 %0, %1, %2;" : "=l"(d) : "l"(a), "l"(b)); return d;
}
__device__ __forceinline__ float pair_sum(ull v){
    float lo = __uint_as_float((unsigned)(v & 0xffffffffu));
    float hi = __uint_as_float((unsigned)(v >> 32));
    return lo + hi;
}

extern __shared__ __align__(16) unsigned char dynsm[];

// ---------------- k0: weight transposes -----------------------------------------------------
__global__ void k0_transpose(const float* __restrict__ W1, const float* __restrict__ W2,
                             const float* __restrict__ Wv)
{
    const int N1 = 27*32;
    const int N2 = 27*16*32;
    const int N3 = 27*16*100;
    for (int i = blockIdx.x*blockDim.x + threadIdx.x; i < N1+N2+N3; i += gridDim.x*blockDim.x){
        if (i < N1){
            int tap = i >> 5, co = i & 31;
            g_w1t[i] = W1[co*27 + tap];
        } else if (i < N1+N2){
            int j = i - N1;
            int tap = j / 512, r = j % 512, cp = r >> 5, co = r & 31;
            g_w2t[j] = make_float2(W2[(co*32 + 2*cp    )*27 + tap],
                                   W2[(co*32 + 2*cp + 1)*27 + tap]);
        } else {
            int k = i - N1 - N2;
            int tap = k / 1600, r = k % 1600, cp = r / 100, co = r % 100;
            g_wvt[k] = make_float2(Wv[(co*32 + 2*cp    )*27 + tap],
                                   Wv[(co*32 + 2*cp + 1)*27 + tap]);
        }
    }
}

// ---------------- k1: conv1(s2) + BN + ReLU + mask  -> g_h1, g_m1 ----------------------------
__global__ __launch_bounds__(128)
void k1_conv1(const float* __restrict__ x, const int* __restrict__ mask0,
              const float* __restrict__ b1, const float* __restrict__ g1,
              const float* __restrict__ bt1, const float* __restrict__ rm1,
              const float* __restrict__ rv1)
{
    __shared__ float sin_[9][65];
    __shared__ int   smk[9][65];
    __shared__ float sw[27*32];
    __shared__ float m1f[32];

    const int yy = blockIdx.x, zz = blockIdx.y, b = blockIdx.z;
    const int t = threadIdx.x, co = t & 31, xg = t >> 5;

    for (int i = t; i < 9*65; i += 128){
        int r = i / 65, xx = i % 65;
        int kz = r / 3, ky = r % 3;
        int iz = 2*zz + kz, iy = 2*yy + ky;
        long off = ((long)(b*65 + iz)*65 + iy)*65 + xx;
        sin_[r][xx] = x[off];
        smk[r][xx]  = mask0[off];
    }
    for (int i = t; i < 27*32; i += 128) sw[i] = g_w1t[i];
    __syncthreads();

    if (t < 32){
        int xo = t, m = 0;
        #pragma unroll
        for (int r = 0; r < 9; r++)
            m |= smk[r][2*xo] | smk[r][2*xo+1] | smk[r][2*xo+2];
        m1f[xo] = m ? 1.0f : 0.0f;
        g_m1[((b*32 + zz)*32 + yy)*32 + xo] = m ? 1 : 0;
    }
    __syncthreads();

    const float s  = g1[co] * rsqrtf(rv1[co] + EPS);
    const float bb = bt1[co] - rm1[co]*s;
    const float bc = b1[co];

    for (int i = 0; i < 8; i++){
        int xo = xg + 4*i;
        float acc = 0.f;
        #pragma unroll
        for (int r = 0; r < 9; r++){
            #pragma unroll
            for (int kx = 0; kx < 3; kx++)
                acc = fmaf(sin_[r][2*xo + kx], sw[(r*3 + kx)*32 + co], acc);
        }
        float h = fmaxf((acc + bc)*s + bb, 0.f) * m1f[xo];
        g_h1[(((long)(b*34 + zz+1)*34 + (yy+1))*34 + (xo+1))*32 + co] = h;
    }
}

// ---------------- k2 v3: z-pair blocks, 256 threads, 50% occ (+ output zero-fill) ------------
// grid (32 y, 16 z-pairs, 2 b). dyn smem: sh[12*34*32]f (52224) | m1f[64]f
#define K2_SMEM (52224 + 256)
__global__ __launch_bounds__(256)
void k2_conv2(const float* __restrict__ b2, const float* __restrict__ g2,
              const float* __restrict__ bt2, const float* __restrict__ rm2,
              const float* __restrict__ rv2, float4* __restrict__ outz)
{
    float* sh  = reinterpret_cast<float*>(dynsm);
    float* m1f = reinterpret_cast<float*>(dynsm + 52224);

    const int yy = blockIdx.x, zp = blockIdx.y, b = blockIdx.z;
    const int zz0 = zp*2;
    const int t = threadIdx.x, co = t & 31, w = t >> 5;
    const int zo = w >> 2, x0 = (w & 3)*8;

    // stage 12 rows [dz 0..3][ky 0..2] of padded h1
    {
        float4* dst = reinterpret_cast<float4*>(sh);
        for (int i = t; i < 3264; i += 256){
            int r = i / 272, rem = i - r*272;
            int dz = r / 3, ky = r - dz*3;
            const float4* src = reinterpret_cast<const float4*>(
                g_h1 + (((long)(b*34 + zz0+dz)*34 + (yy+ky))*34)*32);
            dst[r*272 + rem] = src[rem];
        }
        if (t < 64)
            m1f[t] = g_m1[((b*32 + zz0 + (t>>5))*32 + yy)*32 + (t&31)] ? 1.0f : 0.0f;
    }

    // embedded 220MB output zero-fill: rides DRAM while we compute
    {
        const float4 z4 = make_float4(0.f,0.f,0.f,0.f);
        const int gid = (((b*16 + zp)*32 + yy)*256) + t;   // 0 .. 262143
        for (long i = gid; i < 13731250L; i += 262144L)
            outz[i] = z4;
    }
    __syncthreads();

    const ull* shu = reinterpret_cast<const ull*>(sh);
    const ull* w2u = reinterpret_cast<const ull*>(g_w2t);
    ull acc[8];
    #pragma unroll
    for (int j = 0; j < 8; j++) acc[j] = 0;

    #pragma unroll 1
    for (int r9 = 0; r9 < 9; r9++){
        const int kz = r9 / 3, ky = r9 - kz*3;
        const ull* base = shu + (((zo + kz)*3 + ky)*34 + x0)*16;
        const ull* wb   = w2u + r9*3*512 + co;
        #pragma unroll
        for (int cp = 0; cp < 16; cp++){
            ull h[10];
            #pragma unroll
            for (int i = 0; i < 10; i++) h[i] = base[i*16 + cp];
            ull w0 = __ldg(wb +        cp*32);
            ull w1 = __ldg(wb + 512  + cp*32);
            ull w2v= __ldg(wb + 1024 + cp*32);
            #pragma unroll
            for (int j = 0; j < 8; j++){
                acc[j] = ffma2(h[j  ], w0,  acc[j]);
                acc[j] = ffma2(h[j+1], w1,  acc[j]);
                acc[j] = ffma2(h[j+2], w2v, acc[j]);
            }
        }
    }

    const float s  = g2[co] * rsqrtf(rv2[co] + EPS);
    const float bb = bt2[co] - rm2[co]*s;
    const float bc = b2[co];
    float* out = g_h2 + (((long)(b*32 + zz0 + zo)*32 + yy)*32)*32;
    #pragma unroll
    for (int j = 0; j < 8; j++){
        float v = fmaxf((pair_sum(acc[j]) + bc)*s + bb, 0.f) * m1f[zo*32 + x0 + j];
        out[(x0+j)*32 + co] = v;
    }
}

// ---------------- k3 v5: tap-outer, reg weights, SMEM-staged h tile, branch-free compute -----
// grid (33 z-slices, 8 parity classes, 2 b), 512 threads: slot=t>>7, co=t&127 (<100 active)
// dyn smem: accS f[64*100] (25600) | wS ull[1600] (12800) | hS ull2[64*8] (8192) | alist u16
#define K3_CH    64
#define K3_ACC_B 25600
#define K3_W_B   12800
#define K3_H_B   8192
#define K3_SMEM  (K3_ACC_B + K3_W_B + K3_H_B + 2304)
__global__ __launch_bounds__(512)
void k3_inv(const int* __restrict__ mask0, const float* __restrict__ binv,
            float* __restrict__ out)
{
    float*          accS  = reinterpret_cast<float*>(dynsm);
    ull*            wS    = reinterpret_cast<ull*>(dynsm + K3_ACC_B);
    ulonglong2*     hS    = reinterpret_cast<ulonglong2*>(dynsm + K3_ACC_B + K3_W_B);
    unsigned short* alist = reinterpret_cast<unsigned short*>(dynsm + K3_ACC_B + K3_W_B + K3_H_B);
    __shared__ int s_na;

    const int cls = blockIdx.y;
    const int pz = cls >> 2, py = (cls >> 1) & 1, px = cls & 1;
    const int zz = pz + 2*(int)blockIdx.x;
    const int b  = blockIdx.z;
    if (zz > 64) return;

    const int nKZ = pz ? 1 : 2;
    const int nKY = py ? 1 : 2;
    const int nKX = px ? 1 : 2;
    const int nT  = nKZ*nKY*nKX;
    const int t = threadIdx.x;
    const int slot = t >> 7, co = t & 127;

    if (t == 0) s_na = 0;
    __syncthreads();

    // build active-site list for this (class, zz, b)
    const int nYc = py ? 32 : 33;
    const int nXc = px ? 32 : 33;
    const long plane = 274625L;              // 65^3
    const long zbase = (long)b*plane + (long)zz*4225;
    for (int f = t; f < nYc*nXc; f += 512){
        int j = f / nXc, i = f - j*nXc;
        int yy = py + 2*j, xx = px + 2*i;
        if (mask0[zbase + yy*65 + xx]){
            int p = atomicAdd(&s_na, 1);
            alist[p] = (unsigned short)((yy << 8) | xx);
        }
    }
    __syncthreads();
    const int na = s_na;
    if (na == 0) return;

    const float bc = (co < 100) ? binv[co] : 0.f;
    float* ob = out + ((long)(b*100 + co))*plane + (long)zz*4225;
    const ulonglong2* wsrc = reinterpret_cast<const ulonglong2*>(g_wvt);
    const ulonglong2* h2u2 = reinterpret_cast<const ulonglong2*>(g_h2);
    const int nyx = nKY*nKX;

    for (int c0 = 0; c0 < na; c0 += K3_CH){
        const int nc = min(K3_CH, na - c0);
        __syncthreads();                          // prev writeout / staging done
        {
            float4* a4 = reinterpret_cast<float4*>(accS);
            for (int i = t; i < 1600; i += 512) a4[i] = make_float4(0,0,0,0);
        }

        for (int ti = 0; ti < nT; ti++){
            const int zi = ti / nyx, rr = ti - zi*nyx;
            const int yi = rr / nKX, xi = rr - (rr/nKX)*nKX;
            const int q0 = pz ? ((zz-1) >> 1) : ((zz >> 1) - 1 + zi);
            if ((unsigned)q0 > 31u) continue;     // block-uniform
            const int kz = pz ? 1 : 2*zi;
            const int ky = py ? 1 : 2*yi;
            const int kx = px ? 1 : 2*xi;
            const int tap = (kz*3 + ky)*3 + kx;

            __syncthreads();                      // readers of prev wS/hS done (covers acc-zero too)
            {   // stage weights (12.8KB)
                ulonglong2* d2 = reinterpret_cast<ulonglong2*>(wS);
                const ulonglong2* s2 = wsrc + tap*800;
                for (int i = t; i < 800; i += 512) d2[i] = s2[i];
            }
            {   // stage gathered h tile: 64 sites x 128B, 8 threads/site, zeros if invalid
                const int site = t >> 3, part = t & 7;
                if (site < nc){
                    const int sv = alist[c0 + site];
                    const int yy = sv >> 8, xx = sv & 255;
                    const int q1 = py ? ((yy-1) >> 1) : ((yy >> 1) - 1 + yi);
                    const int qx = px ? ((xx-1) >> 1) : ((xx >> 1) - 1 + xi);
                    ulonglong2 v = make_ulonglong2(0ULL, 0ULL);
                    if (((unsigned)q1 <= 31u) & ((unsigned)qx <= 31u))
                        v = __ldg(h2u2 + ((((long)(b*32 + q0)*32 + q1)*32 + qx)*8 + part));
                    hS[site*8 + part] = v;
                }
            }
            __syncthreads();

            if (co < 100){
                ull wr[16];
                #pragma unroll
                for (int cp = 0; cp < 16; cp++) wr[cp] = wS[cp*100 + co];

                for (int ii = slot; ii < nc; ii += 4){
                    const ulonglong2* hp = hS + ii*8;
                    ull a0 = 0, a1 = 0, a2 = 0, a3 = 0;
                    #pragma unroll
                    for (int k = 0; k < 4; k++){
                        ulonglong2 u = hp[2*k];
                        ulonglong2 v = hp[2*k + 1];
                        a0 = ffma2(u.x, wr[4*k+0], a0);
                        a1 = ffma2(u.y, wr[4*k+1], a1);
                        a2 = ffma2(v.x, wr[4*k+2], a2);
                        a3 = ffma2(v.y, wr[4*k+3], a3);
                    }
                    accS[ii*100 + co] += pair_sum(addf2(addf2(a0,a1), addf2(a2,a3)));
                }
            }
        }
        __syncthreads();

        if (co < 100){
            for (int ii = slot; ii < nc; ii += 4){
                const int sv = alist[c0 + ii];
                ob[(sv >> 8)*65 + (sv & 255)] = accS[ii*100 + co] + bc;
            }
        }
    }
}

// ---------------- launch ---------------------------------------------------------------------
extern "C" void kernel_launch(void* const* d_in, const int* in_sizes, int n_in,
                              void* d_out, int out_size)
{
    const float* x     = (const float*)d_in[0];
    const int*   mask0 = (const int*)  d_in[1];
    const float* W1    = (const float*)d_in[2];
    const float* b1    = (const float*)d_in[3];
    const float* g1    = (const float*)d_in[4];
    const float* bt1   = (const float*)d_in[5];
    const float* rm1   = (const float*)d_in[6];
    const float* rv1   = (const float*)d_in[7];
    const float* W2    = (const float*)d_in[8];
    const float* b2    = (const float*)d_in[9];
    const float* g2    = (const float*)d_in[10];
    const float* bt2   = (const float*)d_in[11];
    const float* rm2   = (const float*)d_in[12];
    const float* rv2   = (const float*)d_in[13];
    const float* Winv  = (const float*)d_in[14];
    const float* binv  = (const float*)d_in[15];
    float* out = (float*)d_out;

    static int attr_set = 0;
    if (!attr_set){
        cudaFuncSetAttribute(k2_conv2, cudaFuncAttributeMaxDynamicSharedMemorySize, K2_SMEM);
        cudaFuncSetAttribute(k3_inv,   cudaFuncAttributeMaxDynamicSharedMemorySize, K3_SMEM);
        attr_set = 1;
    }

    k0_transpose<<<64, 256>>>(W1, W2, Winv);
    k1_conv1<<<dim3(32,32,2), 128>>>(x, mask0, b1, g1, bt1, rm1, rv1);
    k2_conv2<<<dim3(32,16,2), 256, K2_SMEM>>>(b2, g2, bt2, rm2, rv2, (float4*)out);
    k3_inv  <<<dim3(33,8,2), 512, K3_SMEM>>>(mask0, binv, out);
}

// round 8
// speedup vs baseline: 1.7949x; 1.1226x over previous
#include <cuda_runtime.h>
#include <cstdint>

#define EPS 1e-5f
typedef unsigned long long ull;

// ---------------- scratch (device globals; zero-init at load; halos never written) ----------
__device__ __align__(16) float  g_h1[2*34*34*34*32];   // conv1 out, +1 halo all sides, channel-last
__device__ __align__(16) float  g_h2[2*32*32*32*32];   // conv2 out, channel-last [b][z][y][x][ci]
__device__ unsigned char        g_m1[2*32*32*32];      // conv1 output-site mask
__device__ __align__(16) float  g_w1t[27*32];          // W1  -> [tap][co]
__device__ __align__(16) float2 g_w2t[27*16*32];       // W2  -> [tap][ci/2][co] (ci-pair packed)
__device__ __align__(16) float2 g_wvt[27*16*100];      // Winv-> [tap][ci/2][co]

__device__ __forceinline__ ull ffma2(ull a, ull b, ull c){
    ull d; asm("fma.rn.f32x2 %0, %1, %2, %3;" : "=l"(d) : "l"(a), "l"(b), "l"(c)); return d;
}
__device__ __forceinline__ float pair_sum(ull v){
    float lo = __uint_as_float((unsigned)(v & 0xffffffffu));
    float hi = __uint_as_float((unsigned)(v >> 32));
    return lo + hi;
}

// ---------------- k0: weight transposes -----------------------------------------------------
__global__ void k0_transpose(const float* __restrict__ W1, const float* __restrict__ W2,
                             const float* __restrict__ Wv)
{
    const int N1 = 27*32;
    const int N2 = 27*16*32;
    const int N3 = 27*16*100;
    for (int i = blockIdx.x*blockDim.x + threadIdx.x; i < N1+N2+N3; i += gridDim.x*blockDim.x){
        if (i < N1){
            int tap = i >> 5, co = i & 31;
            g_w1t[i] = W1[co*27 + tap];
        } else if (i < N1+N2){
            int j = i - N1;
            int tap = j / 512, r = j % 512, cp = r >> 5, co = r & 31;
            g_w2t[j] = make_float2(W2[(co*32 + 2*cp    )*27 + tap],
                                   W2[(co*32 + 2*cp + 1)*27 + tap]);
        } else {
            int k = i - N1 - N2;
            int tap = k / 1600, r = k % 1600, cp = r / 100, co = r % 100;
            g_wvt[k] = make_float2(Wv[(co*32 + 2*cp    )*27 + tap],
                                   Wv[(co*32 + 2*cp + 1)*27 + tap]);
        }
    }
}

// ---------------- k1: conv1(s2) + BN + ReLU + mask  -> g_h1, g_m1 ----------------------------
__global__ __launch_bounds__(128)
void k1_conv1(const float* __restrict__ x, const int* __restrict__ mask0,
              const float* __restrict__ b1, const float* __restrict__ g1,
              const float* __restrict__ bt1, const float* __restrict__ rm1,
              const float* __restrict__ rv1)
{
    __shared__ float sin_[9][65];
    __shared__ int   smk[9][65];
    __shared__ float sw[27*32];
    __shared__ float m1f[32];

    const int yy = blockIdx.x, zz = blockIdx.y, b = blockIdx.z;
    const int t = threadIdx.x, co = t & 31, xg = t >> 5;

    for (int i = t; i < 9*65; i += 128){
        int r = i / 65, xx = i % 65;
        int kz = r / 3, ky = r % 3;
        int iz = 2*zz + kz, iy = 2*yy + ky;
        long off = ((long)(b*65 + iz)*65 + iy)*65 + xx;
        sin_[r][xx] = x[off];
        smk[r][xx]  = mask0[off];
    }
    for (int i = t; i < 27*32; i += 128) sw[i] = g_w1t[i];
    __syncthreads();

    if (t < 32){
        int xo = t, m = 0;
        #pragma unroll
        for (int r = 0; r < 9; r++)
            m |= smk[r][2*xo] | smk[r][2*xo+1] | smk[r][2*xo+2];
        m1f[xo] = m ? 1.0f : 0.0f;
        g_m1[((b*32 + zz)*32 + yy)*32 + xo] = m ? 1 : 0;
    }
    __syncthreads();

    const float s  = g1[co] * rsqrtf(rv1[co] + EPS);
    const float bb = bt1[co] - rm1[co]*s;
    const float bc = b1[co];

    for (int i = 0; i < 8; i++){
        int xo = xg + 4*i;
        float acc = 0.f;
        #pragma unroll
        for (int r = 0; r < 9; r++){
            #pragma unroll
            for (int kx = 0; kx < 3; kx++)
                acc = fmaf(sin_[r][2*xo + kx], sw[(r*3 + kx)*32 + co], acc);
        }
        float h = fmaxf((acc + bc)*s + bb, 0.f) * m1f[xo];
        g_h1[(((long)(b*34 + zz+1)*34 + (yy+1))*34 + (xo+1))*32 + co] = h;
    }
}

// ---------------- k2: SubMConv 32->32 + BN + ReLU + mask -> g_h2 (+ output zero-fill) --------
// (R6 form: 128 threads, static smem, 4 warps x 8 outputs)
__global__ __launch_bounds__(128)
void k2_conv2(const float* __restrict__ b2, const float* __restrict__ g2,
              const float* __restrict__ bt2, const float* __restrict__ rm2,
              const float* __restrict__ rv2, float4* __restrict__ outz)
{
    __shared__ __align__(16) float sh[9*34*32];
    __shared__ float m1f[32];

    const int yy = blockIdx.x, zz = blockIdx.y, b = blockIdx.z;
    const int t = threadIdx.x, co = t & 31, w = t >> 5;
    const int x0 = w * 8;

    {
        float4* dst = reinterpret_cast<float4*>(sh);
        for (int i = t; i < 2448; i += 128){
            int r = i / 272, rem = i % 272;
            int kz = r / 3, ky = r % 3;
            const float4* src = reinterpret_cast<const float4*>(
                g_h1 + (((long)(b*34 + zz+kz)*34 + (yy+ky))*34)*32);
            dst[r*272 + rem] = src[rem];
        }
        if (t < 32) m1f[t] = g_m1[((b*32 + zz)*32 + yy)*32 + t] ? 1.0f : 0.0f;
    }

    // embedded 220MB output zero-fill: rides DRAM while we compute
    {
        const float4 z4 = make_float4(0.f,0.f,0.f,0.f);
        const int gid = (((b*32 + zz)*32 + yy)*128) + t;
        for (long i = gid; i < 13731250L; i += 262144L)
            outz[i] = z4;
    }
    __syncthreads();

    const ull* shu = reinterpret_cast<const ull*>(sh);
    const ull* w2u = reinterpret_cast<const ull*>(g_w2t);
    ull acc[8];
    #pragma unroll
    for (int j = 0; j < 8; j++) acc[j] = 0;

    for (int row = 0; row < 9; row++){
        const ull* base = shu + (row*34 + x0)*16;
        const ull* wb   = w2u + row*3*512 + co;
        #pragma unroll
        for (int cp = 0; cp < 16; cp++){
            ull h[10];
            #pragma unroll
            for (int i = 0; i < 10; i++) h[i] = base[i*16 + cp];
            ull w0 = __ldg(wb +        cp*32);
            ull w1 = __ldg(wb + 512  + cp*32);
            ull w2v= __ldg(wb + 1024 + cp*32);
            #pragma unroll
            for (int j = 0; j < 8; j++){
                acc[j] = ffma2(h[j  ], w0,  acc[j]);
                acc[j] = ffma2(h[j+1], w1,  acc[j]);
                acc[j] = ffma2(h[j+2], w2v, acc[j]);
            }
        }
    }

    const float s  = g2[co] * rsqrtf(rv2[co] + EPS);
    const float bb = bt2[co] - rm2[co]*s;
    const float bc = b2[co];
    float* out = g_h2 + (((long)(b*32 + zz)*32 + yy)*32)*32;
    #pragma unroll
    for (int j = 0; j < 8; j++){
        float v = fmaxf((pair_sum(acc[j]) + bc)*s + bb, 0.f) * m1f[x0+j];
        out[(x0+j)*32 + co] = v;
    }
}

// ---------------- k3 v6: tap-outer, REGISTER accumulators + register weights -----------------
// grid (33 z-slices, 8 parity classes, 2 b), 512 threads: slot=t>>7, co=t&127 (<100 active)
// per thread: 16 packed accumulators (sites slot+4j), weights LDG->regs per tap.
#define K3_CH 64
__global__ __launch_bounds__(512)
void k3_inv(const int* __restrict__ mask0, const float* __restrict__ binv,
            float* __restrict__ out)
{
    __shared__ __align__(16) ulonglong2 hS[K3_CH*8];   // 8KB gathered h tile
    __shared__ unsigned short alist[1089];
    __shared__ int s_na;

    const int cls = blockIdx.y;
    const int pz = cls >> 2, py = (cls >> 1) & 1, px = cls & 1;
    const int zz = pz + 2*(int)blockIdx.x;
    const int b  = blockIdx.z;
    if (zz > 64) return;

    const int nKZ = pz ? 1 : 2;
    const int nKY = py ? 1 : 2;
    const int nKX = px ? 1 : 2;
    const int nT  = nKZ*nKY*nKX;
    const int nyx = nKY*nKX;
    const int t = threadIdx.x;
    const int slot = t >> 7, co = t & 127;

    if (t == 0) s_na = 0;
    __syncthreads();

    // build active-site list for this (class, zz, b)
    const int nYc = py ? 32 : 33;
    const int nXc = px ? 32 : 33;
    const long plane = 274625L;              // 65^3
    const long zbase = (long)b*plane + (long)zz*4225;
    for (int f = t; f < nYc*nXc; f += 512){
        int j = f / nXc, i = f - j*nXc;
        int yy = py + 2*j, xx = px + 2*i;
        if (mask0[zbase + yy*65 + xx]){
            int p = atomicAdd(&s_na, 1);
            alist[p] = (unsigned short)((yy << 8) | xx);
        }
    }
    __syncthreads();
    const int na = s_na;
    if (na == 0) return;

    const float bc = (co < 100) ? binv[co] : 0.f;
    float* ob = out + ((long)(b*100 + co))*plane + (long)zz*4225;
    const ulonglong2* h2u2 = reinterpret_cast<const ulonglong2*>(g_h2);
    const ull*        wvtU = reinterpret_cast<const ull*>(g_wvt);

    for (int c0 = 0; c0 < na; c0 += K3_CH){
        const int nc = min(K3_CH, na - c0);
        ull acc[16];
        #pragma unroll
        for (int j = 0; j < 16; j++) acc[j] = 0;

        for (int ti = 0; ti < nT; ti++){
            const int zi = ti / nyx, rr = ti - zi*nyx;
            const int yi = rr / nKX, xi = rr - (rr/nKX)*nKX;
            const int q0 = pz ? ((zz-1) >> 1) : ((zz >> 1) - 1 + zi);
            if ((unsigned)q0 > 31u) continue;       // block-uniform
            const int kz = pz ? 1 : 2*zi;
            const int ky = py ? 1 : 2*yi;
            const int kx = px ? 1 : 2*xi;
            const int tap = (kz*3 + ky)*3 + kx;

            __syncthreads();                        // prev-tap compute done reading hS
            {   // stage gathered h tile: nc sites x 128B, 8 threads/site, zeros if invalid
                const int site = t >> 3, part = t & 7;
                if (site < nc){
                    const int sv = alist[c0 + site];
                    const int yy = sv >> 8, xx = sv & 255;
                    const int q1 = py ? ((yy-1) >> 1) : ((yy >> 1) - 1 + yi);
                    const int qx = px ? ((xx-1) >> 1) : ((xx >> 1) - 1 + xi);
                    ulonglong2 v = make_ulonglong2(0ULL, 0ULL);
                    if (((unsigned)q1 <= 31u) & ((unsigned)qx <= 31u))
                        v = __ldg(h2u2 + ((((long)(b*32 + q0)*32 + q1)*32 + qx)*8 + part));
                    hS[site*8 + part] = v;
                }
            }
            __syncthreads();

            if (co < 100){
                ull wr[16];
                const ull* wp = wvtU + tap*1600 + co;
                #pragma unroll
                for (int cp = 0; cp < 16; cp++) wr[cp] = __ldg(wp + cp*100);

                #pragma unroll
                for (int j = 0; j < 16; j++){
                    const int ii = slot + 4*j;
                    if (ii < nc){
                        const ulonglong2* hp = hS + ii*8;
                        ull a = acc[j];
                        #pragma unroll
                        for (int k = 0; k < 4; k++){
                            ulonglong2 u = hp[2*k];
                            ulonglong2 v = hp[2*k + 1];
                            a = ffma2(u.x, wr[4*k+0], a);
                            a = ffma2(u.y, wr[4*k+1], a);
                            a = ffma2(v.x, wr[4*k+2], a);
                            a = ffma2(v.y, wr[4*k+3], a);
                        }
                        acc[j] = a;
                    }
                }
            }
        }

        if (co < 100){
            #pragma unroll
            for (int j = 0; j < 16; j++){
                const int ii = slot + 4*j;
                if (ii < nc){
                    const int sv = alist[c0 + ii];
                    ob[(sv >> 8)*65 + (sv & 255)] = pair_sum(acc[j]) + bc;
                }
            }
        }
    }
}

// ---------------- launch ---------------------------------------------------------------------
extern "C" void kernel_launch(void* const* d_in, const int* in_sizes, int n_in,
                              void* d_out, int out_size)
{
    const float* x     = (const float*)d_in[0];
    const int*   mask0 = (const int*)  d_in[1];
    const float* W1    = (const float*)d_in[2];
    const float* b1    = (const float*)d_in[3];
    const float* g1    = (const float*)d_in[4];
    const float* bt1   = (const float*)d_in[5];
    const float* rm1   = (const float*)d_in[6];
    const float* rv1   = (const float*)d_in[7];
    const float* W2    = (const float*)d_in[8];
    const float* b2    = (const float*)d_in[9];
    const float* g2    = (const float*)d_in[10];
    const float* bt2   = (const float*)d_in[11];
    const float* rm2   = (const float*)d_in[12];
    const float* rv2   = (const float*)d_in[13];
    const float* Winv  = (const float*)d_in[14];
    const float* binv  = (const float*)d_in[15];
    float* out = (float*)d_out;

    k0_transpose<<<64, 256>>>(W1, W2, Winv);
    k1_conv1<<<dim3(32,32,2), 128>>>(x, mask0, b1, g1, bt1, rm1, rv1);
    k2_conv2<<<dim3(32,32,2), 128>>>(b2, g2, bt2, rm2, rv2, (float4*)out);
    k3_inv  <<<dim3(33,8,2), 512>>>(mask0, binv, out);
}